// round 6
// baseline (speedup 1.0000x reference)
#include <cuda_runtime.h>
#include <cuda_bf16.h>
#include <cstdint>
#include <cmath>

// Problem constants
#define E_ 8
#define D_ 1024
#define H_ 4096
#define N_ 8192

#define NTH 256
#define BK  32          // k-tile (bf16 elems)
#define LDP 40          // padded smem row stride (bf16): 80B -> conflict-free LDSM
#define NSTAGE 4

#define TILE_B  (128 * LDP * 2)       // 10240 B per 128x32 bf16 tile
#define STAGE_B (2 * TILE_B)          // A + B per stage = 20480 B
#define SMEM_DYN (NSTAGE * STAGE_B)   // 81920 B

// bf16 copies of inputs + intermediates
__device__ __nv_bfloat16 g_xb  [(size_t)N_ * D_];
__device__ __nv_bfloat16 g_w1b [(size_t)E_ * H_ * D_];
__device__ __nv_bfloat16 g_w3b [(size_t)E_ * H_ * D_];
__device__ __nv_bfloat16 g_w2b [(size_t)E_ * D_ * H_];
__device__ __nv_bfloat16 g_gbuf[(size_t)N_ * H_];   // g = x@w1^T (bf16-rounded)
__device__ __nv_bfloat16 g_hbuf[(size_t)N_ * H_];   // h = gelu(g)*u

// ---------------------------------------------------------------------------
// helpers
// ---------------------------------------------------------------------------
__device__ __forceinline__ uint32_t smem_u32(const void* p) {
    return (uint32_t)__cvta_generic_to_shared(p);
}
__device__ __forceinline__ void cp16(uint32_t saddr, const void* gaddr) {
    asm volatile("cp.async.cg.shared.global [%0], [%1], 16;\n"
                 :: "r"(saddr), "l"(gaddr));
}
__device__ __forceinline__ void cp_commit() {
    asm volatile("cp.async.commit_group;\n");
}
template <int N>
__device__ __forceinline__ void cp_wait() {
    asm volatile("cp.async.wait_group %0;\n" :: "n"(N));
}
__device__ __forceinline__ void ldsm_x4(uint32_t* r, uint32_t addr) {
    asm volatile("ldmatrix.sync.aligned.m8n8.x4.shared.b16 {%0,%1,%2,%3}, [%4];\n"
                 : "=r"(r[0]), "=r"(r[1]), "=r"(r[2]), "=r"(r[3]) : "r"(addr));
}
__device__ __forceinline__ void ldsm_x2(uint32_t* r, uint32_t addr) {
    asm volatile("ldmatrix.sync.aligned.m8n8.x2.shared.b16 {%0,%1}, [%2];\n"
                 : "=r"(r[0]), "=r"(r[1]) : "r"(addr));
}
__device__ __forceinline__ void mma_bf16(float* c, const uint32_t* a, const uint32_t* b) {
    asm volatile("mma.sync.aligned.m16n8k16.row.col.f32.bf16.bf16.f32 "
                 "{%0,%1,%2,%3}, {%4,%5,%6,%7}, {%8,%9}, {%0,%1,%2,%3};\n"
                 : "+f"(c[0]), "+f"(c[1]), "+f"(c[2]), "+f"(c[3])
                 : "r"(a[0]), "r"(a[1]), "r"(a[2]), "r"(a[3]),
                   "r"(b[0]), "r"(b[1]));
}
__device__ __forceinline__ float bfr(float x) {
    return __bfloat162float(__float2bfloat16(x));
}
__device__ __forceinline__ uint32_t pack_bf16(float a, float b) {
    __nv_bfloat162 v = __float22bfloat162_rn(make_float2(a, b));
    return *reinterpret_cast<uint32_t*>(&v);
}
__device__ __forceinline__ float gelu_bf16_chain(float x) {
    float x2  = bfr(x * x);
    float x3  = bfr(x2 * x);
    float t   = bfr(bfr(0.044715f) * x3);
    float s   = bfr(x + t);
    float a   = bfr(bfr(0.7978845608028654f) * s);
    float th  = bfr(tanhf(a));
    float op  = bfr(1.0f + th);
    float cdf = bfr(0.5f * op);
    return bfr(x * cdf);
}
__device__ __forceinline__ int expert_of(const int* counts, int row0) {
    int off = 0, e = 0;
#pragma unroll
    for (int i = 0; i < E_; i++) {
        if (row0 >= off) e = i;
        off += counts[i];
    }
    return e;
}

// ---------------------------------------------------------------------------
// fp32 -> bf16 convert (which: 0=x, 1=w1, 2=w3, 3=w2)
// ---------------------------------------------------------------------------
__global__ __launch_bounds__(NTH)
void cvt_bf16(const float* __restrict__ src, int which, int n4) {
    __nv_bfloat16* dst = (which == 0) ? g_xb
                       : (which == 1) ? g_w1b
                       : (which == 2) ? g_w3b : g_w2b;
    int i = blockIdx.x * NTH + threadIdx.x;
    if (i < n4) {
        float4 v = reinterpret_cast<const float4*>(src)[i];
        uint2 o;
        o.x = pack_bf16(v.x, v.y);
        o.y = pack_bf16(v.z, v.w);
        reinterpret_cast<uint2*>(dst)[i] = o;
    }
}

// ---------------------------------------------------------------------------
// Unified GEMM: C[128x128 tile] = A @ B^T over KDIM, 4-stage cp.async,
// warps 2(m) x 4(n), warp tile 64x32, 2 CTAs/SM.
//   EPI 0: g-pass   A=g_xb  [N,D], B=g_w1b [E,H,D] -> g_gbuf (bf16 acc)
//   EPI 1: u-pass   A=g_xb  [N,D], B=g_w3b [E,H,D] -> g_hbuf = gelu(g)*u
//   EPI 2: out-pass A=g_hbuf[N,H], B=g_w2b [E,D,H] -> out (fp32, bf16-rounded)
// grid = (BROWS/128, N_/128)
// ---------------------------------------------------------------------------
template <int KDIM, int BROWS, int EPI>
__global__ __launch_bounds__(NTH, 2)
void gemm_bf16(const int* __restrict__ counts, float* __restrict__ out)
{
    extern __shared__ char sm[];
    __shared__ int s_e;

    const int tid  = threadIdx.x;
    const int lane = tid & 31;
    const int wid  = tid >> 5;
    const int wm   = wid >> 2;     // 0..1
    const int wn   = wid & 3;      // 0..3
    const int row0 = blockIdx.y * 128;
    const int col0 = blockIdx.x * 128;

    if (tid == 0) s_e = expert_of(counts, row0);
    __syncthreads();
    const int e = s_e;

    const __nv_bfloat16* Abase = (EPI < 2) ? g_xb : g_hbuf;
    const __nv_bfloat16* Bbase = (EPI == 0) ? g_w1b : (EPI == 1) ? g_w3b : g_w2b;
    const __nv_bfloat16* Ag = Abase + (size_t)row0 * KDIM;
    const __nv_bfloat16* Bg = Bbase + ((size_t)e * BROWS + col0) * KDIM;

    const uint32_t sb = smem_u32(sm);

    float acc[4][4][4] = {};

    // stage loader: 2 tiles x (128 rows x 4 chunks of 8 bf16) = 1024 cp16
    auto load_stage = [&](int kt, int st) {
        const int k0 = kt * BK;
        const uint32_t s0 = sb + st * STAGE_B;
#pragma unroll
        for (int i = 0; i < 2; i++) {
            int id = tid + i * NTH;          // 0..511
            int r = id >> 2, ch = id & 3;
            cp16(s0 + (uint32_t)(r * LDP + ch * 8) * 2u,
                 Ag + (size_t)r * KDIM + k0 + ch * 8);
        }
#pragma unroll
        for (int i = 0; i < 2; i++) {
            int id = tid + i * NTH;
            int r = id >> 2, ch = id & 3;
            cp16(s0 + TILE_B + (uint32_t)(r * LDP + ch * 8) * 2u,
                 Bg + (size_t)r * KDIM + k0 + ch * 8);
        }
    };

    auto compute = [&](int st) {
        const uint32_t aB = sb + st * STAGE_B;
        const uint32_t bB = aB + TILE_B;
#pragma unroll
        for (int kk = 0; kk < 2; kk++) {
            const int kc = kk * 16;
            uint32_t a[4][4];
#pragma unroll
            for (int mi = 0; mi < 4; mi++) {
                int r = wm * 64 + mi * 16 + (lane & 15);
                int c = kc + ((lane >> 4) << 3);
                ldsm_x4(a[mi], aB + (uint32_t)(r * LDP + c) * 2u);
            }
#pragma unroll
            for (int ni = 0; ni < 4; ni++) {
                int l16 = lane & 15;
                int r = wn * 32 + ni * 8 + (l16 & 7);
                int c = kc + ((l16 >> 3) << 3);
                uint32_t b[2];
                ldsm_x2(b, bB + (uint32_t)(r * LDP + c) * 2u);
#pragma unroll
                for (int mi = 0; mi < 4; mi++) {
                    mma_bf16(acc[mi][ni], a[mi], b);
                }
            }
        }
    };

    const int NK = KDIM / BK;

    // prologue: 3 stages in flight
#pragma unroll
    for (int s = 0; s < NSTAGE - 1; s++) {
        load_stage(s, s);
        cp_commit();
    }

    for (int kt = 0; kt < NK; kt++) {
        if (kt + NSTAGE - 1 < NK) {
            load_stage(kt + NSTAGE - 1, (kt + NSTAGE - 1) & (NSTAGE - 1));
        }
        cp_commit();
        cp_wait<NSTAGE - 1>();
        __syncthreads();
        compute(kt & (NSTAGE - 1));
        __syncthreads();
    }

    // epilogue
    const int tr = lane >> 2;
    const int tc = (lane & 3) << 1;
#pragma unroll
    for (int mi = 0; mi < 4; mi++) {
#pragma unroll
        for (int ni = 0; ni < 4; ni++) {
#pragma unroll
            for (int rr = 0; rr < 2; rr++) {
                int r = row0 + wm * 64 + mi * 16 + rr * 8 + tr;
                int c = col0 + wn * 32 + ni * 8 + tc;
                float v0 = acc[mi][ni][rr * 2 + 0];
                float v1 = acc[mi][ni][rr * 2 + 1];
                if (EPI == 0) {
                    // g-pass: ragged_dot output is bf16 -> round & store
                    *reinterpret_cast<uint32_t*>(&g_gbuf[(size_t)r * H_ + c]) =
                        pack_bf16(v0, v1);
                } else if (EPI == 1) {
                    // u-pass: h = gelu(g) * u  (all per-op bf16 rounded)
                    uint32_t gv = *reinterpret_cast<const uint32_t*>(
                        &g_gbuf[(size_t)r * H_ + c]);
                    __nv_bfloat162 g2 = *reinterpret_cast<__nv_bfloat162*>(&gv);
                    float g0 = __bfloat162float(g2.x);
                    float g1 = __bfloat162float(g2.y);
                    float u0 = bfr(v0);
                    float u1 = bfr(v1);
                    *reinterpret_cast<uint32_t*>(&g_hbuf[(size_t)r * H_ + c]) =
                        pack_bf16(gelu_bf16_chain(g0) * u0,
                                  gelu_bf16_chain(g1) * u1);
                } else {
                    // out-pass: bf16-round accumulator, store fp32
                    float2 ov;
                    ov.x = bfr(v0);
                    ov.y = bfr(v1);
                    *reinterpret_cast<float2*>(&out[(size_t)r * D_ + c]) = ov;
                }
            }
        }
    }
}

// ---------------------------------------------------------------------------
// launch
// ---------------------------------------------------------------------------
extern "C" void kernel_launch(void* const* d_in, const int* in_sizes, int n_in,
                              void* d_out, int out_size) {
    const float* x      = (const float*)d_in[0];
    const float* w1     = (const float*)d_in[1];
    const float* w2     = (const float*)d_in[2];
    const float* w3     = (const float*)d_in[3];
    const int*   counts = (const int*)d_in[4];
    float* out = (float*)d_out;

    // convert inputs to bf16
    {
        int n4x = (N_ * D_) / 4;
        int n4w = (E_ * H_ * D_) / 4;
        cvt_bf16<<<n4x / NTH, NTH>>>(x,  0, n4x);
        cvt_bf16<<<n4w / NTH, NTH>>>(w1, 1, n4w);
        cvt_bf16<<<n4w / NTH, NTH>>>(w3, 2, n4w);
        cvt_bf16<<<n4w / NTH, NTH>>>(w2, 3, n4w);
    }

    cudaFuncSetAttribute(gemm_bf16<D_, H_, 0>,
                         cudaFuncAttributeMaxDynamicSharedMemorySize, SMEM_DYN);
    cudaFuncSetAttribute(gemm_bf16<D_, H_, 1>,
                         cudaFuncAttributeMaxDynamicSharedMemorySize, SMEM_DYN);
    cudaFuncSetAttribute(gemm_bf16<H_, D_, 2>,
                         cudaFuncAttributeMaxDynamicSharedMemorySize, SMEM_DYN);

    dim3 gg(H_ / 128, N_ / 128);   // (32, 64)
    gemm_bf16<D_, H_, 0><<<gg, NTH, SMEM_DYN>>>(counts, out);   // g-pass
    gemm_bf16<D_, H_, 1><<<gg, NTH, SMEM_DYN>>>(counts, out);   // u-pass + gelu

    dim3 go(D_ / 128, N_ / 128);   // (8, 64)
    gemm_bf16<H_, D_, 2><<<go, NTH, SMEM_DYN>>>(counts, out);   // out-pass
}

// round 7
// speedup vs baseline: 1.1322x; 1.1322x over previous
#include <cuda_runtime.h>
#include <cuda_bf16.h>
#include <cstdint>
#include <cmath>

// Problem constants
#define E_ 8
#define D_ 1024
#define H_ 4096
#define N_ 8192

#define NTH 256
#define BK  64          // k-tile (bf16 elems)
#define LDP 72          // padded smem row stride (bf16): 144B -> conflict-free LDSM
#define NSTAGE 3

#define TILE_B (128 * LDP * 2)        // 18432 B per 128x64 bf16 tile

// bf16 copies of inputs + intermediate h
__device__ __nv_bfloat16 g_xb  [(size_t)N_ * D_];
__device__ __nv_bfloat16 g_w1b [(size_t)E_ * H_ * D_];
__device__ __nv_bfloat16 g_w3b [(size_t)E_ * H_ * D_];
__device__ __nv_bfloat16 g_w2b [(size_t)E_ * D_ * H_];
__device__ __nv_bfloat16 g_hbuf[(size_t)N_ * H_];

// ---------------------------------------------------------------------------
// helpers
// ---------------------------------------------------------------------------
__device__ __forceinline__ uint32_t smem_u32(const void* p) {
    return (uint32_t)__cvta_generic_to_shared(p);
}
__device__ __forceinline__ void cp16(uint32_t saddr, const void* gaddr) {
    asm volatile("cp.async.cg.shared.global [%0], [%1], 16;\n"
                 :: "r"(saddr), "l"(gaddr));
}
__device__ __forceinline__ void cp_commit() {
    asm volatile("cp.async.commit_group;\n");
}
template <int N>
__device__ __forceinline__ void cp_wait() {
    asm volatile("cp.async.wait_group %0;\n" :: "n"(N));
}
__device__ __forceinline__ void ldsm_x4(uint32_t* r, uint32_t addr) {
    asm volatile("ldmatrix.sync.aligned.m8n8.x4.shared.b16 {%0,%1,%2,%3}, [%4];\n"
                 : "=r"(r[0]), "=r"(r[1]), "=r"(r[2]), "=r"(r[3]) : "r"(addr));
}
__device__ __forceinline__ void mma_bf16(float* c, const uint32_t* a, const uint32_t* b) {
    asm volatile("mma.sync.aligned.m16n8k16.row.col.f32.bf16.bf16.f32 "
                 "{%0,%1,%2,%3}, {%4,%5,%6,%7}, {%8,%9}, {%0,%1,%2,%3};\n"
                 : "+f"(c[0]), "+f"(c[1]), "+f"(c[2]), "+f"(c[3])
                 : "r"(a[0]), "r"(a[1]), "r"(a[2]), "r"(a[3]),
                   "r"(b[0]), "r"(b[1]));
}
__device__ __forceinline__ float bfr(float x) {
    return __bfloat162float(__float2bfloat16(x));
}
__device__ __forceinline__ uint32_t pack_bf16(float a, float b) {
    __nv_bfloat162 v = __float22bfloat162_rn(make_float2(a, b));
    return *reinterpret_cast<uint32_t*>(&v);
}
__device__ __forceinline__ float gelu_bf16_chain(float x) {
    float x2  = bfr(x * x);
    float x3  = bfr(x2 * x);
    float t   = bfr(bfr(0.044715f) * x3);
    float s   = bfr(x + t);
    float a   = bfr(bfr(0.7978845608028654f) * s);
    float th  = bfr(tanhf(a));
    float op  = bfr(1.0f + th);
    float cdf = bfr(0.5f * op);
    return bfr(x * cdf);
}
__device__ __forceinline__ int expert_of(const int* counts, int row0) {
    int off = 0, e = 0;
#pragma unroll
    for (int i = 0; i < E_; i++) {
        if (row0 >= off) e = i;
        off += counts[i];
    }
    return e;
}

// ---------------------------------------------------------------------------
// fp32 -> bf16 convert (which: 0=x, 1=w1, 2=w3, 3=w2)
// ---------------------------------------------------------------------------
__global__ __launch_bounds__(NTH)
void cvt_bf16(const float* __restrict__ src, int which, int n4) {
    __nv_bfloat16* dst = (which == 0) ? g_xb
                       : (which == 1) ? g_w1b
                       : (which == 2) ? g_w3b : g_w2b;
    int i = blockIdx.x * NTH + threadIdx.x;
    if (i < n4) {
        float4 v = reinterpret_cast<const float4*>(src)[i];
        uint2 o;
        o.x = pack_bf16(v.x, v.y);
        o.y = pack_bf16(v.z, v.w);
        reinterpret_cast<uint2*>(dst)[i] = o;
    }
}

// ---------------------------------------------------------------------------
// GEMM 1 (fused): g = x@w1^T, u = x@w3^T, h = gelu(g)*u -> g_hbuf (bf16)
// CTA 128x128, BK=64, 3-stage cp.async, single sync per k-iter.
// warps 2(m) x 4(n), warp tile 64x32 per matrix.
// grid = (H/128, N_/128) = (32, 64)
// ---------------------------------------------------------------------------
#define ST1B (3 * TILE_B)             // A + B1 + B3 per stage = 55296 B

__global__ __launch_bounds__(NTH, 1)
void moe_g1(const int* __restrict__ counts)
{
    extern __shared__ char sm[];
    __shared__ int s_e;

    const int tid  = threadIdx.x;
    const int lane = tid & 31;
    const int wid  = tid >> 5;
    const int wm   = wid >> 2;     // 0..1
    const int wn   = wid & 3;      // 0..3
    const int row0 = blockIdx.y * 128;
    const int col0 = blockIdx.x * 128;

    if (tid == 0) s_e = expert_of(counts, row0);
    __syncthreads();
    const int e = s_e;

    const __nv_bfloat16* Ag  = g_xb  + (size_t)row0 * D_;
    const __nv_bfloat16* B1g = g_w1b + ((size_t)e * H_ + col0) * D_;
    const __nv_bfloat16* B3g = g_w3b + ((size_t)e * H_ + col0) * D_;

    const uint32_t sb = smem_u32(sm);

    float cg[4][4][4] = {};
    float cu[4][4][4] = {};

    // stage loader: 3 tiles x (128 rows x 8 chunks) = 12 cp16/thread
    auto load_stage = [&](int kt, int st) {
        const int k0 = kt * BK;
        const uint32_t s0 = sb + st * ST1B;
#pragma unroll
        for (int i = 0; i < 4; i++) {
            int id = tid + i * NTH;
            int r = id >> 3, ch = id & 7;
            cp16(s0 + (uint32_t)(r * LDP + ch * 8) * 2u,
                 Ag + (size_t)r * D_ + k0 + ch * 8);
        }
#pragma unroll
        for (int i = 0; i < 4; i++) {
            int id = tid + i * NTH;
            int r = id >> 3, ch = id & 7;
            cp16(s0 + TILE_B + (uint32_t)(r * LDP + ch * 8) * 2u,
                 B1g + (size_t)r * D_ + k0 + ch * 8);
        }
#pragma unroll
        for (int i = 0; i < 4; i++) {
            int id = tid + i * NTH;
            int r = id >> 3, ch = id & 7;
            cp16(s0 + 2 * TILE_B + (uint32_t)(r * LDP + ch * 8) * 2u,
                 B3g + (size_t)r * D_ + k0 + ch * 8);
        }
    };

    auto compute = [&](int st) {
        const uint32_t aB  = sb + st * ST1B;
        const uint32_t b1B = aB + TILE_B;
        const uint32_t b3B = aB + 2 * TILE_B;
#pragma unroll
        for (int kk = 0; kk < 4; kk++) {
            const int kc = kk * 16;
            uint32_t a[4][4];
#pragma unroll
            for (int mi = 0; mi < 4; mi++) {
                int r = wm * 64 + mi * 16 + (lane & 15);
                int c = kc + ((lane >> 4) << 3);
                ldsm_x4(a[mi], aB + (uint32_t)(r * LDP + c) * 2u);
            }
#pragma unroll
            for (int ni2 = 0; ni2 < 2; ni2++) {
                // x4 LDSM covers ni = 2*ni2 and 2*ni2+1 (matrices: n0k0,n0k8,n1k0,n1k8)
                int q  = lane >> 3, lr = lane & 7;
                int r  = wn * 32 + (ni2 * 2 + (q >> 1)) * 8 + lr;
                int c  = kc + (q & 1) * 8;
                uint32_t b1[4], b3[4];
                ldsm_x4(b1, b1B + (uint32_t)(r * LDP + c) * 2u);
                ldsm_x4(b3, b3B + (uint32_t)(r * LDP + c) * 2u);
#pragma unroll
                for (int mi = 0; mi < 4; mi++) {
                    mma_bf16(cg[mi][ni2 * 2 + 0], a[mi], b1 + 0);
                    mma_bf16(cg[mi][ni2 * 2 + 1], a[mi], b1 + 2);
                    mma_bf16(cu[mi][ni2 * 2 + 0], a[mi], b3 + 0);
                    mma_bf16(cu[mi][ni2 * 2 + 1], a[mi], b3 + 2);
                }
            }
        }
    };

    const int NK = D_ / BK;   // 16

    load_stage(0, 0); cp_commit();
    load_stage(1, 1); cp_commit();

    for (int kt = 0; kt < NK; kt++) {
        cp_wait<1>();               // stage kt complete
        __syncthreads();
        if (kt + 2 < NK) load_stage(kt + 2, (kt + 2) % NSTAGE);
        cp_commit();                // empty group at tail keeps count semantics
        compute(kt % NSTAGE);
    }

    // epilogue: bf16-rounded gelu(g)*u -> hbuf
    const int tr = lane >> 2;
    const int tc = (lane & 3) << 1;
#pragma unroll
    for (int mi = 0; mi < 4; mi++) {
#pragma unroll
        for (int ni = 0; ni < 4; ni++) {
#pragma unroll
            for (int rr = 0; rr < 2; rr++) {
                int r = row0 + wm * 64 + mi * 16 + rr * 8 + tr;
                int c = col0 + wn * 32 + ni * 8 + tc;
                float g0 = bfr(cg[mi][ni][rr * 2 + 0]);
                float g1 = bfr(cg[mi][ni][rr * 2 + 1]);
                float u0 = bfr(cu[mi][ni][rr * 2 + 0]);
                float u1 = bfr(cu[mi][ni][rr * 2 + 1]);
                uint32_t hv = pack_bf16(gelu_bf16_chain(g0) * u0,
                                        gelu_bf16_chain(g1) * u1);
                *reinterpret_cast<uint32_t*>(&g_hbuf[(size_t)r * H_ + c]) = hv;
            }
        }
    }
}

// ---------------------------------------------------------------------------
// GEMM 2: out = h @ w2^T. CTA 128x128, BK=64, 3-stage, 2 CTAs/SM.
// grid = (D/128, N_/128) = (8, 64)
// ---------------------------------------------------------------------------
#define ST2B (2 * TILE_B)             // 36864 B per stage

__global__ __launch_bounds__(NTH, 2)
void moe_g2(const int* __restrict__ counts, float* __restrict__ out)
{
    extern __shared__ char sm[];
    __shared__ int s_e;

    const int tid  = threadIdx.x;
    const int lane = tid & 31;
    const int wid  = tid >> 5;
    const int wm   = wid >> 2;
    const int wn   = wid & 3;
    const int row0 = blockIdx.y * 128;
    const int col0 = blockIdx.x * 128;

    if (tid == 0) s_e = expert_of(counts, row0);
    __syncthreads();
    const int e = s_e;

    const __nv_bfloat16* Ag = g_hbuf + (size_t)row0 * H_;
    const __nv_bfloat16* Bg = g_w2b  + ((size_t)e * D_ + col0) * H_;

    const uint32_t sb = smem_u32(sm);

    float co[4][4][4] = {};

    auto load_stage = [&](int kt, int st) {
        const int k0 = kt * BK;
        const uint32_t s0 = sb + st * ST2B;
#pragma unroll
        for (int i = 0; i < 4; i++) {
            int id = tid + i * NTH;
            int r = id >> 3, ch = id & 7;
            cp16(s0 + (uint32_t)(r * LDP + ch * 8) * 2u,
                 Ag + (size_t)r * H_ + k0 + ch * 8);
        }
#pragma unroll
        for (int i = 0; i < 4; i++) {
            int id = tid + i * NTH;
            int r = id >> 3, ch = id & 7;
            cp16(s0 + TILE_B + (uint32_t)(r * LDP + ch * 8) * 2u,
                 Bg + (size_t)r * H_ + k0 + ch * 8);
        }
    };

    auto compute = [&](int st) {
        const uint32_t aB = sb + st * ST2B;
        const uint32_t bB = aB + TILE_B;
#pragma unroll
        for (int kk = 0; kk < 4; kk++) {
            const int kc = kk * 16;
            uint32_t a[4][4];
#pragma unroll
            for (int mi = 0; mi < 4; mi++) {
                int r = wm * 64 + mi * 16 + (lane & 15);
                int c = kc + ((lane >> 4) << 3);
                ldsm_x4(a[mi], aB + (uint32_t)(r * LDP + c) * 2u);
            }
#pragma unroll
            for (int ni2 = 0; ni2 < 2; ni2++) {
                int q  = lane >> 3, lr = lane & 7;
                int r  = wn * 32 + (ni2 * 2 + (q >> 1)) * 8 + lr;
                int c  = kc + (q & 1) * 8;
                uint32_t b[4];
                ldsm_x4(b, bB + (uint32_t)(r * LDP + c) * 2u);
#pragma unroll
                for (int mi = 0; mi < 4; mi++) {
                    mma_bf16(co[mi][ni2 * 2 + 0], a[mi], b + 0);
                    mma_bf16(co[mi][ni2 * 2 + 1], a[mi], b + 2);
                }
            }
        }
    };

    const int NK = H_ / BK;   // 64

    load_stage(0, 0); cp_commit();
    load_stage(1, 1); cp_commit();

    for (int kt = 0; kt < NK; kt++) {
        cp_wait<1>();
        __syncthreads();
        if (kt + 2 < NK) load_stage(kt + 2, (kt + 2) % NSTAGE);
        cp_commit();
        compute(kt % NSTAGE);
    }

    // epilogue: round accumulator through bf16, store fp32
    const int tr = lane >> 2;
    const int tc = (lane & 3) << 1;
#pragma unroll
    for (int mi = 0; mi < 4; mi++) {
#pragma unroll
        for (int ni = 0; ni < 4; ni++) {
#pragma unroll
            for (int rr = 0; rr < 2; rr++) {
                int r = row0 + wm * 64 + mi * 16 + rr * 8 + tr;
                int c = col0 + wn * 32 + ni * 8 + tc;
                float2 ov;
                ov.x = bfr(co[mi][ni][rr * 2 + 0]);
                ov.y = bfr(co[mi][ni][rr * 2 + 1]);
                *reinterpret_cast<float2*>(&out[(size_t)r * D_ + c]) = ov;
            }
        }
    }
}

// ---------------------------------------------------------------------------
// launch
// ---------------------------------------------------------------------------
extern "C" void kernel_launch(void* const* d_in, const int* in_sizes, int n_in,
                              void* d_out, int out_size) {
    const float* x      = (const float*)d_in[0];
    const float* w1     = (const float*)d_in[1];
    const float* w2     = (const float*)d_in[2];
    const float* w3     = (const float*)d_in[3];
    const int*   counts = (const int*)d_in[4];
    float* out = (float*)d_out;

    // convert inputs to bf16
    {
        int n4x = (N_ * D_) / 4;
        int n4w = (E_ * H_ * D_) / 4;
        cvt_bf16<<<n4x / NTH, NTH>>>(x,  0, n4x);
        cvt_bf16<<<n4w / NTH, NTH>>>(w1, 1, n4w);
        cvt_bf16<<<n4w / NTH, NTH>>>(w3, 2, n4w);
        cvt_bf16<<<n4w / NTH, NTH>>>(w2, 3, n4w);
    }

    cudaFuncSetAttribute(moe_g1, cudaFuncAttributeMaxDynamicSharedMemorySize,
                         NSTAGE * ST1B);
    cudaFuncSetAttribute(moe_g2, cudaFuncAttributeMaxDynamicSharedMemorySize,
                         NSTAGE * ST2B);

    dim3 g1(H_ / 128, N_ / 128);   // (32, 64)
    moe_g1<<<g1, NTH, NSTAGE * ST1B>>>(counts);

    dim3 g2(D_ / 128, N_ / 128);   // (8, 64)
    moe_g2<<<g2, NTH, NSTAGE * ST2B>>>(counts, out);
}